// round 15
// baseline (speedup 1.0000x reference)
#include <cuda_runtime.h>

#define Bn 64
#define Nn 512
#define Kk 32
#define Dd 64
#define BN_TOTAL (Bn*Nn)   // 32768
#define EPSf 1e-5f
#define NEG_SLOPE 0.2f
#define NEG_INFf -1e9f

// ---- scratch (static device globals; no allocation) ----
__device__ float g_cos[Nn * Nn];                // 1 MB
__device__ int   g_topk[Nn * Kk];
__device__ float g_xl[(size_t)BN_TOTAL * Dd];   // 8 MB
__device__ float g_ci[BN_TOTAL];
__device__ float g_cj[BN_TOTAL];

// ---- f32x2 packed helpers ----
__device__ __forceinline__ unsigned long long fma2(unsigned long long a,
                                                   unsigned long long b,
                                                   unsigned long long c) {
    unsigned long long d;
    asm("fma.rn.f32x2 %0, %1, %2, %3;" : "=l"(d) : "l"(a), "l"(b), "l"(c));
    return d;
}
__device__ __forceinline__ unsigned long long dup2(float x) {
    unsigned long long d; unsigned int u = __float_as_uint(x);
    asm("mov.b64 %0, {%1, %2};" : "=l"(d) : "r"(u), "r"(u));
    return d;
}
__device__ __forceinline__ float2 unpack2(unsigned long long v) {
    unsigned int lo, hi;
    asm("mov.b64 {%0, %1}, %2;" : "=r"(lo), "=r"(hi) : "l"(v));
    return make_float2(__uint_as_float(lo), __uint_as_float(hi));
}
__device__ __forceinline__ unsigned long long umax64(unsigned long long a,
                                                     unsigned long long b) {
    return a > b ? a : b;
}
__device__ __forceinline__ unsigned long long umin64(unsigned long long a,
                                                     unsigned long long b) {
    return a < b ? a : b;
}

// ---------------------------------------------------------------
// Kernel 1: cosine tile (16 i x 32 j), inline norms. 512 blocks
// (2x blocks/SM vs the 256-block shape -> better latency hiding).
// ---------------------------------------------------------------
__global__ void __launch_bounds__(256)
k_cos(const float* __restrict__ emb) {
    __shared__ float s_A[16][65];
    __shared__ float s_B[32][65];
    __shared__ float s_invA[16];
    __shared__ float s_invB[32];

    const int tid = threadIdx.x;
    const int w = tid >> 5, t = tid & 31;
    const int i0 = (blockIdx.x >> 4) * 16;   // 32 i-tiles
    const int j0 = (blockIdx.x & 15) * 32;   // 16 j-tiles

    for (int idx = tid; idx < 16 * 32; idx += 256) {
        int r = idx >> 5, c = idx & 31;
        float2 va = ((const float2*)(emb + (i0 + r) * Dd))[c];
        s_A[r][2 * c] = va.x; s_A[r][2 * c + 1] = va.y;
    }
    for (int idx = tid; idx < 32 * 32; idx += 256) {
        int r = idx >> 5, c = idx & 31;
        float2 vb = ((const float2*)(emb + (j0 + r) * Dd))[c];
        s_B[r][2 * c] = vb.x; s_B[r][2 * c + 1] = vb.y;
    }
    __syncthreads();

    if (tid < 16) {
        float s2 = 0.f;
#pragma unroll 8
        for (int k = 0; k < Dd; k++) { float e = s_A[tid][k]; s2 = fmaf(e, e, s2); }
        s_invA[tid] = rsqrtf(s2);
    } else if (tid < 48) {
        const int r = tid - 16;
        float s2 = 0.f;
#pragma unroll 8
        for (int k = 0; k < Dd; k++) { float e = s_B[r][k]; s2 = fmaf(e, e, s2); }
        s_invB[r] = rsqrtf(s2);
    }
    __syncthreads();

    // warp w -> i-rows {2w, 2w+1}; lane t -> column j0+t
    float acc0 = 0.f, acc1 = 0.f;
    const int ia = 2 * w, ib = 2 * w + 1;
#pragma unroll 8
    for (int k = 0; k < Dd; k++) {
        const float b = s_B[t][k];               // (t+k)%32 conflict-free
        acc0 = fmaf(s_A[ia][k], b, acc0);        // broadcast
        acc1 = fmaf(s_A[ib][k], b, acc1);
    }

    const float invj = s_invB[t];
    g_cos[(i0 + ia) * Nn + j0 + t] = acc0 * s_invA[ia] * invj;
    g_cos[(i0 + ib) * Nn + j0 + t] = acc1 * s_invA[ib] * invj;
}

// ---------------------------------------------------------------
// Body A: bitonic top-K for one row (8 warps, R13/R14-validated).
// ---------------------------------------------------------------
__device__ __forceinline__ void topk_body(int i, int tid) {
    __shared__ unsigned long long s_k[14][32];

    const int w = tid >> 5, l = tid & 31;
    const float* crow = g_cos + i * Nn;

    const int j0 = w * 64 + 2 * l;
    const float2 c2 = *(const float2*)(crow + j0);
    unsigned int b0 = __float_as_uint(c2.x);
    b0 = (b0 & 0x80000000u) ? ~b0 : (b0 | 0x80000000u);
    unsigned int b1 = __float_as_uint(c2.y);
    b1 = (b1 & 0x80000000u) ? ~b1 : (b1 | 0x80000000u);
    unsigned long long v0 = ((unsigned long long)b0 << 32) | (unsigned int)(Nn - 1 - j0);
    unsigned long long v1 = ((unsigned long long)b1 << 32) | (unsigned int)(Nn - 2 - j0);

#pragma unroll
    for (int k = 2; k <= 32; k <<= 1) {
#pragma unroll
        for (int j = k >> 1; j > 0; j >>= 1) {
            const bool keepMax = (((l & j) == 0) == ((l & k) == 0));
            unsigned long long o0 = __shfl_xor_sync(0xFFFFFFFFu, v0, j);
            unsigned long long o1 = __shfl_xor_sync(0xFFFFFFFFu, v1, j);
            v0 = keepMax ? umax64(v0, o0) : umin64(v0, o0);
            v1 = keepMax ? umax64(v1, o1) : umin64(v1, o1);
        }
    }

    unsigned long long m = umax64(v0, __shfl_xor_sync(0xFFFFFFFFu, v1, 31));
#pragma unroll
    for (int j = 16; j > 0; j >>= 1) {
        unsigned long long o = __shfl_xor_sync(0xFFFFFFFFu, m, j);
        m = ((l & j) == 0) ? umax64(m, o) : umin64(m, o);
    }
    s_k[w][l] = m;
    __syncthreads();

    if (w < 4) {
        unsigned long long a = s_k[2 * w][l];
        unsigned long long b = s_k[2 * w + 1][31 - l];
        unsigned long long m2 = umax64(a, b);
#pragma unroll
        for (int j = 16; j > 0; j >>= 1) {
            unsigned long long o = __shfl_xor_sync(0xFFFFFFFFu, m2, j);
            m2 = ((l & j) == 0) ? umax64(m2, o) : umin64(m2, o);
        }
        s_k[8 + w][l] = m2;
    }
    __syncthreads();

    if (w < 2) {
        unsigned long long a = s_k[8 + 2 * w][l];
        unsigned long long b = s_k[8 + 2 * w + 1][31 - l];
        unsigned long long m3 = umax64(a, b);
#pragma unroll
        for (int j = 16; j > 0; j >>= 1) {
            unsigned long long o = __shfl_xor_sync(0xFFFFFFFFu, m3, j);
            m3 = ((l & j) == 0) ? umax64(m3, o) : umin64(m3, o);
        }
        s_k[12 + w][l] = m3;
    }
    __syncthreads();

    if (w == 0) {
        unsigned long long a = s_k[12][l];
        unsigned long long b = s_k[13][31 - l];
        unsigned long long m4 = umax64(a, b);
        g_topk[i * Kk + l] = Nn - 1 - (int)(m4 & 0xFFFFFFFFu);
    }
}

// ---------------------------------------------------------------
// Body B: xl = x @ W^T + ci/cj, edot folded in (R13/R14-validated).
// ---------------------------------------------------------------
#define XT_STRIDE 66
__device__ __forceinline__ void xl_body(
    int blk, int tid,
    const float* __restrict__ x, const float* __restrict__ W,
    const float* __restrict__ emb,
    const float* __restrict__ att_i, const float* __restrict__ att_j,
    const float* __restrict__ att_em_i, const float* __restrict__ att_em_j) {
    __shared__ float s_W[Dd][Dd + 1];
    __shared__ float s_xt[Dd][XT_STRIDE];
    __shared__ float s_edi[64], s_edj[64];

    const int w = tid >> 5, t = tid & 31;
    const int node_blk = blk * 64;
    const int l0base = node_blk & (Nn - 1);

    for (int idx = tid; idx < Dd * Dd; idx += 256) {
        int d = idx >> 6, k = idx & 63;
        s_W[k][d] = W[idx];
    }
    {
        const float4* xs = (const float4*)(x + (size_t)node_blk * Dd);
#pragma unroll
        for (int v = tid; v < 1024; v += 256) {
            float4 val = xs[v];
            int n = v >> 4, q = (v & 15) * 4;
            float* dst = &s_xt[0][0] + q * XT_STRIDE + n;
            dst[0]             = val.x;
            dst[XT_STRIDE]     = val.y;
            dst[2 * XT_STRIDE] = val.z;
            dst[3 * XT_STRIDE] = val.w;
        }
    }
    if (tid < 64) {
        const float* er = emb + (size_t)(l0base + tid) * Dd;
        float di = 0.f, dj = 0.f;
#pragma unroll 8
        for (int d = 0; d < Dd; d++) {
            float e = __ldg(er + d);
            di = fmaf(e, __ldg(att_em_i + d), di);
            dj = fmaf(e, __ldg(att_em_j + d), dj);
        }
        s_edi[tid] = di;
        s_edj[tid] = dj;
    }
    __syncthreads();

    const float ai0 = att_i[t], ai1 = att_i[t + 32];
    const float aj0 = att_j[t], aj1 = att_j[t + 32];

    unsigned long long accA[4] = {0ull, 0ull, 0ull, 0ull};
    unsigned long long accB[4] = {0ull, 0ull, 0ull, 0ull};
    const int nl0 = w * 8;

#pragma unroll 16
    for (int k = 0; k < Dd; k++) {
        const unsigned long long wd0 = dup2(s_W[k][t]);
        const unsigned long long wd1 = dup2(s_W[k][t + 32]);
        const unsigned long long* xrow =
            (const unsigned long long*)(&s_xt[0][0] + k * XT_STRIDE + nl0);
#pragma unroll
        for (int p = 0; p < 4; p++) {
            const unsigned long long xp = xrow[p];
            accA[p] = fma2(xp, wd0, accA[p]);
            accB[p] = fma2(xp, wd1, accB[p]);
        }
    }

#pragma unroll
    for (int p = 0; p < 4; p++) {
        const float2 a = unpack2(accA[p]);
        const float2 b = unpack2(accB[p]);
        const int n0 = node_blk + nl0 + 2 * p;
        const int n1 = n0 + 1;
        g_xl[(size_t)n0 * Dd + t]      = a.x;
        g_xl[(size_t)n0 * Dd + t + 32] = b.x;
        g_xl[(size_t)n1 * Dd + t]      = a.y;
        g_xl[(size_t)n1 * Dd + t + 32] = b.y;

        float pi0 = a.x * ai0 + b.x * ai1, pj0 = a.x * aj0 + b.x * aj1;
        float pi1 = a.y * ai0 + b.y * ai1, pj1 = a.y * aj0 + b.y * aj1;
#pragma unroll
        for (int o = 16; o > 0; o >>= 1) {
            pi0 += __shfl_xor_sync(0xFFFFFFFFu, pi0, o);
            pj0 += __shfl_xor_sync(0xFFFFFFFFu, pj0, o);
            pi1 += __shfl_xor_sync(0xFFFFFFFFu, pi1, o);
            pj1 += __shfl_xor_sync(0xFFFFFFFFu, pj1, o);
        }
        if (t == 0) {
            const int ll0 = nl0 + 2 * p, ll1 = ll0 + 1;
            g_ci[n0] = pi0 + s_edi[ll0];
            g_cj[n0] = pj0 + s_edj[ll0];
            g_ci[n1] = pi1 + s_edi[ll1];
            g_cj[n1] = pj1 + s_edj[ll1];
        }
    }
}

// ---------------------------------------------------------------
// Kernel 2 (FUSED LAUNCH): blocks 0..511 -> topk; 512..1023 -> xl.
// ---------------------------------------------------------------
__global__ void __launch_bounds__(256)
k_mid(const float* __restrict__ x, const float* __restrict__ W,
      const float* __restrict__ emb,
      const float* __restrict__ att_i, const float* __restrict__ att_j,
      const float* __restrict__ att_em_i, const float* __restrict__ att_em_j) {
    if (blockIdx.x < Nn) {
        topk_body(blockIdx.x, threadIdx.x);
    } else {
        xl_body(blockIdx.x - Nn, threadIdx.x, x, W, emb,
                att_i, att_j, att_em_i, att_em_j);
    }
}

// ---------------------------------------------------------------
// Kernel 3: attention + epilogue. 1024 blocks x 512 threads,
// launch_bounds(512,3) [R13]. Gather reads TWO edges per LDS.128
// (aligned rows of 34 float2) with PRE-SHIFTED source offsets.
// ---------------------------------------------------------------
__global__ void __launch_bounds__(512, 3)
k_attn(const float* __restrict__ emb,
       const float* __restrict__ gnn_bias,
       const float* __restrict__ bn1_gamma, const float* __restrict__ bn1_beta,
       const float* __restrict__ bn1_mean,  const float* __restrict__ bn1_var,
       const float* __restrict__ bno_gamma, const float* __restrict__ bno_beta,
       const float* __restrict__ bno_mean,  const float* __restrict__ bno_var,
       const float* __restrict__ out_W,     const float* __restrict__ out_b,
       float* __restrict__ out) {
    __shared__ float s_cj[Nn];
    __shared__ __align__(16) float2 s_ws[16][2][34];   // 34 -> 272B rows, 16B-aligned

    const int tid = threadIdx.x;
    const int w = tid >> 5, t = tid & 31;
    const int batch = blockIdx.x >> 4;
    const int lbase = (blockIdx.x & 15) * 32;
    const int base  = batch * Nn;

    s_cj[tid] = g_cj[base + tid];
    __syncthreads();

    const int li0 = lbase + 2 * w, li1 = li0 + 1;
    const int node0 = base + li0,  node1 = base + li1;

    const float ci0 = g_ci[node0];
    const float ci1 = g_ci[node1];
    const int s0 = g_topk[li0 * Kk + t];
    const int s1 = g_topk[li1 * Kk + t];
    const bool ok0 = (s0 != li0);
    const bool ok1 = (s1 != li1);

    float lg0 = ci0 + s_cj[s0];
    float lg1 = ci1 + s_cj[s1];
    lg0 = (lg0 >= 0.f) ? lg0 : NEG_SLOPE * lg0;
    lg1 = (lg1 >= 0.f) ? lg1 : NEG_SLOPE * lg1;
    if (!ok0) lg0 = NEG_INFf;
    if (!ok1) lg1 = NEG_INFf;

    float lgs0 = ci0 + s_cj[li0];
    float lgs1 = ci1 + s_cj[li1];
    lgs0 = (lgs0 >= 0.f) ? lgs0 : NEG_SLOPE * lgs0;
    lgs1 = (lgs1 >= 0.f) ? lgs1 : NEG_SLOPE * lgs1;

    float mx0 = lg0, mx1 = lg1;
#pragma unroll
    for (int o = 16; o > 0; o >>= 1) {
        mx0 = fmaxf(mx0, __shfl_xor_sync(0xFFFFFFFFu, mx0, o));
        mx1 = fmaxf(mx1, __shfl_xor_sync(0xFFFFFFFFu, mx1, o));
    }
    mx0 = fmaxf(mx0, lgs0);
    mx1 = fmaxf(mx1, lgs1);

    const float ex0  = ok0 ? __expf(lg0 - mx0) : 0.0f;
    const float ex1  = ok1 ? __expf(lg1 - mx1) : 0.0f;
    const float exs0 = __expf(lgs0 - mx0);
    const float exs1 = __expf(lgs1 - mx1);
    float sum0 = ex0, sum1 = ex1;
#pragma unroll
    for (int o = 16; o > 0; o >>= 1) {
        sum0 += __shfl_xor_sync(0xFFFFFFFFu, sum0, o);
        sum1 += __shfl_xor_sync(0xFFFFFFFFu, sum1, o);
    }
    const float inv0 = 1.0f / (sum0 + exs0);
    const float inv1 = 1.0f / (sum1 + exs1);

    // store weight + PRE-SHIFTED float offset (src * Dd)
    s_ws[w][0][t] = make_float2(ex0 * inv0, __int_as_float(s0 << 6));
    s_ws[w][1][t] = make_float2(ex1 * inv1, __int_as_float(s1 << 6));
    if (t == 0) {
        s_ws[w][0][32] = make_float2(exs0 * inv0, __int_as_float(li0 << 6));
        s_ws[w][1][32] = make_float2(exs1 * inv1, __int_as_float(li1 << 6));
    }
    __syncwarp();

    const int half = t >> 4;
    const int q    = t & 15;
    const int li   = half ? li1 : li0;
    const int node = half ? node1 : node0;
    const float* xb = g_xl + (size_t)base * Dd + 4 * q;
    const float2* wsrow = s_ws[w][half];

    float4 acc = make_float4(0.f, 0.f, 0.f, 0.f);
#pragma unroll 8
    for (int e2 = 0; e2 < 16; e2++) {                   // 2 edges per iter
        const float4 wp = *(const float4*)(&wsrow[2 * e2]);   // LDS.128 broadcast
        const float4 v0 = *(const float4*)(xb + __float_as_int(wp.y));
        const float4 v1 = *(const float4*)(xb + __float_as_int(wp.w));
        acc.x = fmaf(wp.x, v0.x, acc.x);
        acc.y = fmaf(wp.x, v0.y, acc.y);
        acc.z = fmaf(wp.x, v0.z, acc.z);
        acc.w = fmaf(wp.x, v0.w, acc.w);
        acc.x = fmaf(wp.z, v1.x, acc.x);
        acc.y = fmaf(wp.z, v1.y, acc.y);
        acc.z = fmaf(wp.z, v1.z, acc.z);
        acc.w = fmaf(wp.z, v1.w, acc.w);
    }
    {   // self edge (slot 32)
        const float2 wsl = wsrow[32];
        const float4 vs = *(const float4*)(xb + __float_as_int(wsl.y));
        acc.x = fmaf(wsl.x, vs.x, acc.x);
        acc.y = fmaf(wsl.x, vs.y, acc.y);
        acc.z = fmaf(wsl.x, vs.z, acc.z);
        acc.w = fmaf(wsl.x, vs.w, acc.w);
    }

    const float4 gb = ((const float4*)gnn_bias)[q];
    const float4 g1 = ((const float4*)bn1_gamma)[q];
    const float4 b1 = ((const float4*)bn1_beta)[q];
    const float4 m1 = ((const float4*)bn1_mean)[q];
    const float4 v1 = ((const float4*)bn1_var)[q];
    const float4 go = ((const float4*)bno_gamma)[q];
    const float4 bo = ((const float4*)bno_beta)[q];
    const float4 mo = ((const float4*)bno_mean)[q];
    const float4 vo = ((const float4*)bno_var)[q];
    const float4 ow = ((const float4*)out_W)[q];
    const float4 em = *(const float4*)(emb + li * Dd + 4 * q);

    const float s1x = rsqrtf(v1.x + EPSf) * g1.x;
    const float s1y = rsqrtf(v1.y + EPSf) * g1.y;
    const float s1z = rsqrtf(v1.z + EPSf) * g1.z;
    const float s1w = rsqrtf(v1.w + EPSf) * g1.w;
    const float sox = rsqrtf(vo.x + EPSf) * go.x;
    const float soy = rsqrtf(vo.y + EPSf) * go.y;
    const float soz = rsqrtf(vo.z + EPSf) * go.z;
    const float sow = rsqrtf(vo.w + EPSf) * go.w;

    float h0 = fmaxf((acc.x + gb.x - m1.x) * s1x + b1.x, 0.f) * em.x;
    float h1 = fmaxf((acc.y + gb.y - m1.y) * s1y + b1.y, 0.f) * em.y;
    float h2 = fmaxf((acc.z + gb.z - m1.z) * s1z + b1.z, 0.f) * em.z;
    float h3 = fmaxf((acc.w + gb.w - m1.w) * s1w + b1.w, 0.f) * em.w;
    h0 = fmaxf(fmaf(h0, sox, bo.x - mo.x * sox), 0.f);
    h1 = fmaxf(fmaf(h1, soy, bo.y - mo.y * soy), 0.f);
    h2 = fmaxf(fmaf(h2, soz, bo.z - mo.z * soz), 0.f);
    h3 = fmaxf(fmaf(h3, sow, bo.w - mo.w * sow), 0.f);

    float p = h0 * ow.x + h1 * ow.y + h2 * ow.z + h3 * ow.w;
#pragma unroll
    for (int o = 8; o > 0; o >>= 1)
        p += __shfl_xor_sync(0xFFFFFFFFu, p, o);
    if (q == 0) out[node] = p + out_b[0];
}

// ---------------------------------------------------------------
extern "C" void kernel_launch(void* const* d_in, const int* in_sizes, int n_in,
                              void* d_out, int out_size) {
    (void)in_sizes; (void)n_in; (void)out_size;
    const float* data      = (const float*)d_in[0];
    /* d_in[1] = org_edge_index — unused by the model */
    const float* emb       = (const float*)d_in[2];
    const float* lin_W     = (const float*)d_in[3];
    const float* att_i     = (const float*)d_in[4];
    const float* att_j     = (const float*)d_in[5];
    const float* att_em_i  = (const float*)d_in[6];
    const float* att_em_j  = (const float*)d_in[7];
    const float* gnn_bias  = (const float*)d_in[8];
    const float* bn1_gamma = (const float*)d_in[9];
    const float* bn1_beta  = (const float*)d_in[10];
    const float* bn1_mean  = (const float*)d_in[11];
    const float* bn1_var   = (const float*)d_in[12];
    const float* bno_gamma = (const float*)d_in[13];
    const float* bno_beta  = (const float*)d_in[14];
    const float* bno_mean  = (const float*)d_in[15];
    const float* bno_var   = (const float*)d_in[16];
    const float* out_W     = (const float*)d_in[17];
    const float* out_b     = (const float*)d_in[18];
    float* out = (float*)d_out;

    k_cos<<<512, 256>>>(emb);
    k_mid<<<Nn + BN_TOTAL / 64, 256>>>(data, lin_W, emb,
                                       att_i, att_j, att_em_i, att_em_j);
    k_attn<<<BN_TOTAL / 32, 512>>>(emb, gnn_bias,
                                   bn1_gamma, bn1_beta, bn1_mean, bn1_var,
                                   bno_gamma, bno_beta, bno_mean, bno_var,
                                   out_W, out_b, out);
}

// round 16
// speedup vs baseline: 1.0715x; 1.0715x over previous
#include <cuda_runtime.h>

#define Bn 64
#define Nn 512
#define Kk 32
#define Dd 64
#define BN_TOTAL (Bn*Nn)   // 32768
#define EPSf 1e-5f
#define NEG_SLOPE 0.2f
#define NEG_INFf -1e9f

// ---- scratch (static device globals; no allocation) ----
__device__ float g_cos[Nn * Nn];                // 1 MB
__device__ int   g_topk[Nn * Kk];
__device__ float g_xl[(size_t)BN_TOTAL * Dd];   // 8 MB
__device__ float g_ci[BN_TOTAL];
__device__ float g_cj[BN_TOTAL];

// ---- f32x2 packed helpers ----
__device__ __forceinline__ unsigned long long fma2(unsigned long long a,
                                                   unsigned long long b,
                                                   unsigned long long c) {
    unsigned long long d;
    asm("fma.rn.f32x2 %0, %1, %2, %3;" : "=l"(d) : "l"(a), "l"(b), "l"(c));
    return d;
}
__device__ __forceinline__ unsigned long long dup2(float x) {
    unsigned long long d; unsigned int u = __float_as_uint(x);
    asm("mov.b64 %0, {%1, %2};" : "=l"(d) : "r"(u), "r"(u));
    return d;
}
__device__ __forceinline__ float2 unpack2(unsigned long long v) {
    unsigned int lo, hi;
    asm("mov.b64 {%0, %1}, %2;" : "=r"(lo), "=r"(hi) : "l"(v));
    return make_float2(__uint_as_float(lo), __uint_as_float(hi));
}
__device__ __forceinline__ unsigned long long umax64(unsigned long long a,
                                                     unsigned long long b) {
    return a > b ? a : b;
}
__device__ __forceinline__ unsigned long long umin64(unsigned long long a,
                                                     unsigned long long b) {
    return a < b ? a : b;
}

// ---------------------------------------------------------------
// Kernel 1: cosine tile (32 i x 32 j), inline norms. 256 blocks.
// (R14-proven shape — staging-bound, bigger tiles win.)
// ---------------------------------------------------------------
__global__ void __launch_bounds__(256)
k_cos(const float* __restrict__ emb) {
    __shared__ float s_A[32][65];
    __shared__ float s_B[32][65];
    __shared__ float s_invA[32];
    __shared__ float s_invB[32];

    const int tid = threadIdx.x;
    const int w = tid >> 5, t = tid & 31;
    const int i0 = (blockIdx.x >> 4) * 32;
    const int j0 = (blockIdx.x & 15) * 32;

    for (int idx = tid; idx < 32 * 32; idx += 256) {
        int r = idx >> 5, c = idx & 31;
        float2 va = ((const float2*)(emb + (i0 + r) * Dd))[c];
        s_A[r][2 * c] = va.x; s_A[r][2 * c + 1] = va.y;
        float2 vb = ((const float2*)(emb + (j0 + r) * Dd))[c];
        s_B[r][2 * c] = vb.x; s_B[r][2 * c + 1] = vb.y;
    }
    __syncthreads();

    if (tid < 32) {
        float s2 = 0.f;
#pragma unroll 8
        for (int k = 0; k < Dd; k++) { float e = s_A[tid][k]; s2 = fmaf(e, e, s2); }
        s_invA[tid] = rsqrtf(s2);
    } else if (tid < 64) {
        const int r = tid - 32;
        float s2 = 0.f;
#pragma unroll 8
        for (int k = 0; k < Dd; k++) { float e = s_B[r][k]; s2 = fmaf(e, e, s2); }
        s_invB[r] = rsqrtf(s2);
    }
    __syncthreads();

    float acc[4] = {0.f, 0.f, 0.f, 0.f};
#pragma unroll 8
    for (int k = 0; k < Dd; k++) {
        const float b = s_B[t][k];
#pragma unroll
        for (int a = 0; a < 4; a++)
            acc[a] = fmaf(s_A[w * 4 + a][k], b, acc[a]);
    }

    const float invj = s_invB[t];
#pragma unroll
    for (int a = 0; a < 4; a++) {
        const int irow = i0 + w * 4 + a;
        g_cos[irow * Nn + j0 + t] = acc[a] * s_invA[w * 4 + a] * invj;
    }
}

// ---------------------------------------------------------------
// Body A: bitonic top-K for one row (8 warps, R13/R14-validated).
// ---------------------------------------------------------------
__device__ __forceinline__ void topk_body(int i, int tid) {
    __shared__ unsigned long long s_k[14][32];

    const int w = tid >> 5, l = tid & 31;
    const float* crow = g_cos + i * Nn;

    const int j0 = w * 64 + 2 * l;
    const float2 c2 = *(const float2*)(crow + j0);
    unsigned int b0 = __float_as_uint(c2.x);
    b0 = (b0 & 0x80000000u) ? ~b0 : (b0 | 0x80000000u);
    unsigned int b1 = __float_as_uint(c2.y);
    b1 = (b1 & 0x80000000u) ? ~b1 : (b1 | 0x80000000u);
    unsigned long long v0 = ((unsigned long long)b0 << 32) | (unsigned int)(Nn - 1 - j0);
    unsigned long long v1 = ((unsigned long long)b1 << 32) | (unsigned int)(Nn - 2 - j0);

#pragma unroll
    for (int k = 2; k <= 32; k <<= 1) {
#pragma unroll
        for (int j = k >> 1; j > 0; j >>= 1) {
            const bool keepMax = (((l & j) == 0) == ((l & k) == 0));
            unsigned long long o0 = __shfl_xor_sync(0xFFFFFFFFu, v0, j);
            unsigned long long o1 = __shfl_xor_sync(0xFFFFFFFFu, v1, j);
            v0 = keepMax ? umax64(v0, o0) : umin64(v0, o0);
            v1 = keepMax ? umax64(v1, o1) : umin64(v1, o1);
        }
    }

    unsigned long long m = umax64(v0, __shfl_xor_sync(0xFFFFFFFFu, v1, 31));
#pragma unroll
    for (int j = 16; j > 0; j >>= 1) {
        unsigned long long o = __shfl_xor_sync(0xFFFFFFFFu, m, j);
        m = ((l & j) == 0) ? umax64(m, o) : umin64(m, o);
    }
    s_k[w][l] = m;
    __syncthreads();

    if (w < 4) {
        unsigned long long a = s_k[2 * w][l];
        unsigned long long b = s_k[2 * w + 1][31 - l];
        unsigned long long m2 = umax64(a, b);
#pragma unroll
        for (int j = 16; j > 0; j >>= 1) {
            unsigned long long o = __shfl_xor_sync(0xFFFFFFFFu, m2, j);
            m2 = ((l & j) == 0) ? umax64(m2, o) : umin64(m2, o);
        }
        s_k[8 + w][l] = m2;
    }
    __syncthreads();

    if (w < 2) {
        unsigned long long a = s_k[8 + 2 * w][l];
        unsigned long long b = s_k[8 + 2 * w + 1][31 - l];
        unsigned long long m3 = umax64(a, b);
#pragma unroll
        for (int j = 16; j > 0; j >>= 1) {
            unsigned long long o = __shfl_xor_sync(0xFFFFFFFFu, m3, j);
            m3 = ((l & j) == 0) ? umax64(m3, o) : umin64(m3, o);
        }
        s_k[12 + w][l] = m3;
    }
    __syncthreads();

    if (w == 0) {
        unsigned long long a = s_k[12][l];
        unsigned long long b = s_k[13][31 - l];
        unsigned long long m4 = umax64(a, b);
        g_topk[i * Kk + l] = Nn - 1 - (int)(m4 & 0xFFFFFFFFu);
    }
}

// ---------------------------------------------------------------
// Body B: xl = x @ W^T + ci/cj, edot folded in (R13/R14-validated).
// ---------------------------------------------------------------
#define XT_STRIDE 66
__device__ __forceinline__ void xl_body(
    int blk, int tid,
    const float* __restrict__ x, const float* __restrict__ W,
    const float* __restrict__ emb,
    const float* __restrict__ att_i, const float* __restrict__ att_j,
    const float* __restrict__ att_em_i, const float* __restrict__ att_em_j) {
    __shared__ float s_W[Dd][Dd + 1];
    __shared__ float s_xt[Dd][XT_STRIDE];
    __shared__ float s_edi[64], s_edj[64];

    const int w = tid >> 5, t = tid & 31;
    const int node_blk = blk * 64;
    const int l0base = node_blk & (Nn - 1);

    for (int idx = tid; idx < Dd * Dd; idx += 256) {
        int d = idx >> 6, k = idx & 63;
        s_W[k][d] = W[idx];
    }
    {
        const float4* xs = (const float4*)(x + (size_t)node_blk * Dd);
#pragma unroll
        for (int v = tid; v < 1024; v += 256) {
            float4 val = xs[v];
            int n = v >> 4, q = (v & 15) * 4;
            float* dst = &s_xt[0][0] + q * XT_STRIDE + n;
            dst[0]             = val.x;
            dst[XT_STRIDE]     = val.y;
            dst[2 * XT_STRIDE] = val.z;
            dst[3 * XT_STRIDE] = val.w;
        }
    }
    if (tid < 64) {
        const float* er = emb + (size_t)(l0base + tid) * Dd;
        float di = 0.f, dj = 0.f;
#pragma unroll 8
        for (int d = 0; d < Dd; d++) {
            float e = __ldg(er + d);
            di = fmaf(e, __ldg(att_em_i + d), di);
            dj = fmaf(e, __ldg(att_em_j + d), dj);
        }
        s_edi[tid] = di;
        s_edj[tid] = dj;
    }
    __syncthreads();

    const float ai0 = att_i[t], ai1 = att_i[t + 32];
    const float aj0 = att_j[t], aj1 = att_j[t + 32];

    unsigned long long accA[4] = {0ull, 0ull, 0ull, 0ull};
    unsigned long long accB[4] = {0ull, 0ull, 0ull, 0ull};
    const int nl0 = w * 8;

#pragma unroll 16
    for (int k = 0; k < Dd; k++) {
        const unsigned long long wd0 = dup2(s_W[k][t]);
        const unsigned long long wd1 = dup2(s_W[k][t + 32]);
        const unsigned long long* xrow =
            (const unsigned long long*)(&s_xt[0][0] + k * XT_STRIDE + nl0);
#pragma unroll
        for (int p = 0; p < 4; p++) {
            const unsigned long long xp = xrow[p];
            accA[p] = fma2(xp, wd0, accA[p]);
            accB[p] = fma2(xp, wd1, accB[p]);
        }
    }

#pragma unroll
    for (int p = 0; p < 4; p++) {
        const float2 a = unpack2(accA[p]);
        const float2 b = unpack2(accB[p]);
        const int n0 = node_blk + nl0 + 2 * p;
        const int n1 = n0 + 1;
        g_xl[(size_t)n0 * Dd + t]      = a.x;
        g_xl[(size_t)n0 * Dd + t + 32] = b.x;
        g_xl[(size_t)n1 * Dd + t]      = a.y;
        g_xl[(size_t)n1 * Dd + t + 32] = b.y;

        float pi0 = a.x * ai0 + b.x * ai1, pj0 = a.x * aj0 + b.x * aj1;
        float pi1 = a.y * ai0 + b.y * ai1, pj1 = a.y * aj0 + b.y * aj1;
#pragma unroll
        for (int o = 16; o > 0; o >>= 1) {
            pi0 += __shfl_xor_sync(0xFFFFFFFFu, pi0, o);
            pj0 += __shfl_xor_sync(0xFFFFFFFFu, pj0, o);
            pi1 += __shfl_xor_sync(0xFFFFFFFFu, pi1, o);
            pj1 += __shfl_xor_sync(0xFFFFFFFFu, pj1, o);
        }
        if (t == 0) {
            const int ll0 = nl0 + 2 * p, ll1 = ll0 + 1;
            g_ci[n0] = pi0 + s_edi[ll0];
            g_cj[n0] = pj0 + s_edj[ll0];
            g_ci[n1] = pi1 + s_edi[ll1];
            g_cj[n1] = pj1 + s_edj[ll1];
        }
    }
}

// ---------------------------------------------------------------
// Kernel 2 (FUSED LAUNCH): blocks 0..511 -> topk; 512..1023 -> xl.
// ---------------------------------------------------------------
__global__ void __launch_bounds__(256)
k_mid(const float* __restrict__ x, const float* __restrict__ W,
      const float* __restrict__ emb,
      const float* __restrict__ att_i, const float* __restrict__ att_j,
      const float* __restrict__ att_em_i, const float* __restrict__ att_em_j) {
    if (blockIdx.x < Nn) {
        topk_body(blockIdx.x, threadIdx.x);
    } else {
        xl_body(blockIdx.x - Nn, threadIdx.x, x, W, emb,
                att_i, att_j, att_em_i, att_em_j);
    }
}

// ---------------------------------------------------------------
// Kernel 3: attention + epilogue (R14 structure). Single change:
// s_ws stores PRE-SHIFTED float offsets (src << 6) so the 33-edge
// gather loop has zero shift/IMAD address work per edge.
// ---------------------------------------------------------------
__global__ void __launch_bounds__(512, 3)
k_attn(const float* __restrict__ emb,
       const float* __restrict__ gnn_bias,
       const float* __restrict__ bn1_gamma, const float* __restrict__ bn1_beta,
       const float* __restrict__ bn1_mean,  const float* __restrict__ bn1_var,
       const float* __restrict__ bno_gamma, const float* __restrict__ bno_beta,
       const float* __restrict__ bno_mean,  const float* __restrict__ bno_var,
       const float* __restrict__ out_W,     const float* __restrict__ out_b,
       float* __restrict__ out) {
    __shared__ float  s_cj[Nn];
    __shared__ float2 s_ws[16][2][33];

    const int tid = threadIdx.x;
    const int w = tid >> 5, t = tid & 31;
    const int batch = blockIdx.x >> 4;
    const int lbase = (blockIdx.x & 15) * 32;
    const int base  = batch * Nn;

    s_cj[tid] = g_cj[base + tid];
    __syncthreads();

    const int li0 = lbase + 2 * w, li1 = li0 + 1;
    const int node0 = base + li0,  node1 = base + li1;

    const float ci0 = g_ci[node0];
    const float ci1 = g_ci[node1];
    const int s0 = g_topk[li0 * Kk + t];
    const int s1 = g_topk[li1 * Kk + t];
    const bool ok0 = (s0 != li0);
    const bool ok1 = (s1 != li1);

    float lg0 = ci0 + s_cj[s0];
    float lg1 = ci1 + s_cj[s1];
    lg0 = (lg0 >= 0.f) ? lg0 : NEG_SLOPE * lg0;
    lg1 = (lg1 >= 0.f) ? lg1 : NEG_SLOPE * lg1;
    if (!ok0) lg0 = NEG_INFf;
    if (!ok1) lg1 = NEG_INFf;

    float lgs0 = ci0 + s_cj[li0];
    float lgs1 = ci1 + s_cj[li1];
    lgs0 = (lgs0 >= 0.f) ? lgs0 : NEG_SLOPE * lgs0;
    lgs1 = (lgs1 >= 0.f) ? lgs1 : NEG_SLOPE * lgs1;

    float mx0 = lg0, mx1 = lg1;
#pragma unroll
    for (int o = 16; o > 0; o >>= 1) {
        mx0 = fmaxf(mx0, __shfl_xor_sync(0xFFFFFFFFu, mx0, o));
        mx1 = fmaxf(mx1, __shfl_xor_sync(0xFFFFFFFFu, mx1, o));
    }
    mx0 = fmaxf(mx0, lgs0);
    mx1 = fmaxf(mx1, lgs1);

    const float ex0  = ok0 ? __expf(lg0 - mx0) : 0.0f;
    const float ex1  = ok1 ? __expf(lg1 - mx1) : 0.0f;
    const float exs0 = __expf(lgs0 - mx0);
    const float exs1 = __expf(lgs1 - mx1);
    float sum0 = ex0, sum1 = ex1;
#pragma unroll
    for (int o = 16; o > 0; o >>= 1) {
        sum0 += __shfl_xor_sync(0xFFFFFFFFu, sum0, o);
        sum1 += __shfl_xor_sync(0xFFFFFFFFu, sum1, o);
    }
    const float inv0 = 1.0f / (sum0 + exs0);
    const float inv1 = 1.0f / (sum1 + exs1);

    // weight + PRE-SHIFTED element offset (src * Dd)
    s_ws[w][0][t] = make_float2(ex0 * inv0, __int_as_float(s0 << 6));
    s_ws[w][1][t] = make_float2(ex1 * inv1, __int_as_float(s1 << 6));
    if (t == 0) {
        s_ws[w][0][32] = make_float2(exs0 * inv0, __int_as_float(li0 << 6));
        s_ws[w][1][32] = make_float2(exs1 * inv1, __int_as_float(li1 << 6));
    }
    __syncwarp();

    const int half = t >> 4;
    const int q    = t & 15;
    const int li   = half ? li1 : li0;
    const int node = half ? node1 : node0;
    const float* xb = g_xl + (size_t)base * Dd + 4 * q;
    const float2* wsrow = s_ws[w][half];

    float4 acc = make_float4(0.f, 0.f, 0.f, 0.f);
#pragma unroll 11
    for (int e = 0; e < 33; e++) {
        const float2 ws = wsrow[e];                       // LDS.64 broadcast
        const float4 v = *(const float4*)(xb + __float_as_int(ws.y));
        acc.x = fmaf(ws.x, v.x, acc.x);
        acc.y = fmaf(ws.x, v.y, acc.y);
        acc.z = fmaf(ws.x, v.z, acc.z);
        acc.w = fmaf(ws.x, v.w, acc.w);
    }

    const float4 gb = ((const float4*)gnn_bias)[q];
    const float4 g1 = ((const float4*)bn1_gamma)[q];
    const float4 b1 = ((const float4*)bn1_beta)[q];
    const float4 m1 = ((const float4*)bn1_mean)[q];
    const float4 v1 = ((const float4*)bn1_var)[q];
    const float4 go = ((const float4*)bno_gamma)[q];
    const float4 bo = ((const float4*)bno_beta)[q];
    const float4 mo = ((const float4*)bno_mean)[q];
    const float4 vo = ((const float4*)bno_var)[q];
    const float4 ow = ((const float4*)out_W)[q];
    const float4 em = *(const float4*)(emb + li * Dd + 4 * q);

    const float s1x = rsqrtf(v1.x + EPSf) * g1.x;
    const float s1y = rsqrtf(v1.y + EPSf) * g1.y;
    const float s1z = rsqrtf(v1.z + EPSf) * g1.z;
    const float s1w = rsqrtf(v1.w + EPSf) * g1.w;
    const float sox = rsqrtf(vo.x + EPSf) * go.x;
    const float soy = rsqrtf(vo.y + EPSf) * go.y;
    const float soz = rsqrtf(vo.z + EPSf) * go.z;
    const float sow = rsqrtf(vo.w + EPSf) * go.w;

    float h0 = fmaxf((acc.x + gb.x - m1.x) * s1x + b1.x, 0.f) * em.x;
    float h1 = fmaxf((acc.y + gb.y - m1.y) * s1y + b1.y, 0.f) * em.y;
    float h2 = fmaxf((acc.z + gb.z - m1.z) * s1z + b1.z, 0.f) * em.z;
    float h3 = fmaxf((acc.w + gb.w - m1.w) * s1w + b1.w, 0.f) * em.w;
    h0 = fmaxf(fmaf(h0, sox, bo.x - mo.x * sox), 0.f);
    h1 = fmaxf(fmaf(h1, soy, bo.y - mo.y * soy), 0.f);
    h2 = fmaxf(fmaf(h2, soz, bo.z - mo.z * soz), 0.f);
    h3 = fmaxf(fmaf(h3, sow, bo.w - mo.w * sow), 0.f);

    float p = h0 * ow.x + h1 * ow.y + h2 * ow.z + h3 * ow.w;
#pragma unroll
    for (int o = 8; o > 0; o >>= 1)
        p += __shfl_xor_sync(0xFFFFFFFFu, p, o);
    if (q == 0) out[node] = p + out_b[0];
}

// ---------------------------------------------------------------
extern "C" void kernel_launch(void* const* d_in, const int* in_sizes, int n_in,
                              void* d_out, int out_size) {
    (void)in_sizes; (void)n_in; (void)out_size;
    const float* data      = (const float*)d_in[0];
    /* d_in[1] = org_edge_index — unused by the model */
    const float* emb       = (const float*)d_in[2];
    const float* lin_W     = (const float*)d_in[3];
    const float* att_i     = (const float*)d_in[4];
    const float* att_j     = (const float*)d_in[5];
    const float* att_em_i  = (const float*)d_in[6];
    const float* att_em_j  = (const float*)d_in[7];
    const float* gnn_bias  = (const float*)d_in[8];
    const float* bn1_gamma = (const float*)d_in[9];
    const float* bn1_beta  = (const float*)d_in[10];
    const float* bn1_mean  = (const float*)d_in[11];
    const float* bn1_var   = (const float*)d_in[12];
    const float* bno_gamma = (const float*)d_in[13];
    const float* bno_beta  = (const float*)d_in[14];
    const float* bno_mean  = (const float*)d_in[15];
    const float* bno_var   = (const float*)d_in[16];
    const float* out_W     = (const float*)d_in[17];
    const float* out_b     = (const float*)d_in[18];
    float* out = (float*)d_out;

    k_cos<<<256, 256>>>(emb);
    k_mid<<<Nn + BN_TOTAL / 64, 256>>>(data, lin_W, emb,
                                       att_i, att_j, att_em_i, att_em_j);
    k_attn<<<BN_TOTAL / 32, 512>>>(emb, gnn_bias,
                                   bn1_gamma, bn1_beta, bn1_mean, bn1_var,
                                   bno_gamma, bno_beta, bno_mean, bno_var,
                                   out_W, out_b, out);
}